// round 15
// baseline (speedup 1.0000x reference)
#include <cuda_runtime.h>

#define MAX_N 100000
#define MAX_E 1600000

// ---------------- scratch (static __device__ arrays) ----------------------
__device__ float g_h1  [MAX_N * 64];
__device__ float g_als1[MAX_N * 4];
__device__ float g_ald1[MAX_N * 4];
__device__ float g_out1[MAX_N * 64];
__device__ float g_h2  [MAX_N * 128];
__device__ float g_als2[MAX_N * 4];
__device__ float g_ald2[MAX_N * 4];
__device__ int   g_rowptr[MAX_N + 1];
__device__ int   g_cursor[MAX_N];
__device__ int   g_bsum[128];
__device__ int   g_ssrc[MAX_E];

// ---------------- GEMM + fused attention logits (proven 48us) -------------
template<int K, int NC, bool ADD_BIAS>
__global__ __launch_bounds__(256)
void gemm_kernel(const float* __restrict__ A, const float* __restrict__ W,
                 const float* __restrict__ abias,
                 const float* __restrict__ a_src, const float* __restrict__ a_dst,
                 float* __restrict__ C,
                 float* __restrict__ als, float* __restrict__ ald, int M)
{
    constexpr int KC = 32;
    __shared__ float As[128][KC + 4];
    __shared__ float Bs[KC][64];

    const int tx = threadIdx.x & 15;
    const int ty = threadIdx.x >> 4;
    const int row0 = blockIdx.x * 128;
    const int col0 = blockIdx.y * 64;

    float acc[8][4];
#pragma unroll
    for (int i = 0; i < 8; i++)
#pragma unroll
        for (int j = 0; j < 4; j++) acc[i][j] = 0.f;

    for (int kk = 0; kk < K; kk += KC) {
#pragma unroll
        for (int i = 0; i < 4; i++) {
            int idx = threadIdx.x + i * 256;
            int r = idx >> 3, c4 = idx & 7;
            float4 v = make_float4(0.f, 0.f, 0.f, 0.f);
            int gr = row0 + r;
            if (gr < M)
                v = *(const float4*)(A + (size_t)gr * K + kk + c4 * 4);
            if (ADD_BIAS) {
                v.x += abias[kk + c4 * 4 + 0];
                v.y += abias[kk + c4 * 4 + 1];
                v.z += abias[kk + c4 * 4 + 2];
                v.w += abias[kk + c4 * 4 + 3];
            }
            *(float4*)&As[r][c4 * 4] = v;
        }
#pragma unroll
        for (int i = 0; i < 2; i++) {
            int idx = threadIdx.x + i * 256;
            int r = idx >> 4, c4 = idx & 15;
            *(float4*)&Bs[r][c4 * 4] =
                *(const float4*)(W + (size_t)(kk + r) * NC + col0 + c4 * 4);
        }
        __syncthreads();

#pragma unroll
        for (int k = 0; k < KC; k++) {
            float4 b = *(float4*)&Bs[k][tx * 4];
#pragma unroll
            for (int i = 0; i < 8; i++) {
                float a = As[ty * 8 + i][k];
                acc[i][0] += a * b.x;
                acc[i][1] += a * b.y;
                acc[i][2] += a * b.z;
                acc[i][3] += a * b.w;
            }
        }
        __syncthreads();
    }

    // ---- store C ----
#pragma unroll
    for (int i = 0; i < 8; i++) {
        int gr = row0 + ty * 8 + i;
        if (gr < M)
            *(float4*)(C + (size_t)gr * NC + col0 + tx * 4) =
                make_float4(acc[i][0], acc[i][1], acc[i][2], acc[i][3]);
    }

    // ---- fused logits ----
    constexpr int CPH = NC / 4;
    constexpr int G   = CPH / 4;
    const int gcol0 = col0 + tx * 4;
    const int head = gcol0 / CPH;
    float asv[4], adv[4];
#pragma unroll
    for (int j = 0; j < 4; j++) {
        asv[j] = a_src[gcol0 + j];
        adv[j] = a_dst[gcol0 + j];
    }
#pragma unroll
    for (int i = 0; i < 8; i++) {
        float s1 = acc[i][0] * asv[0] + acc[i][1] * asv[1]
                 + acc[i][2] * asv[2] + acc[i][3] * asv[3];
        float s2 = acc[i][0] * adv[0] + acc[i][1] * adv[1]
                 + acc[i][2] * adv[2] + acc[i][3] * adv[3];
#pragma unroll
        for (int off = 1; off < G; off <<= 1) {
            s1 += __shfl_xor_sync(0xffffffffu, s1, off);
            s2 += __shfl_xor_sync(0xffffffffu, s2, off);
        }
        int gr = row0 + ty * 8 + i;
        if ((tx & (G - 1)) == 0 && gr < M) {
            als[(size_t)gr * 4 + head] = s1;
            ald[(size_t)gr * 4 + head] = s2;
        }
    }
}

// ---------------- CSR build ------------------------------------------------
__global__ void hist_kernel(const int* __restrict__ de, int E, int* __restrict__ cnt)
{
    int e = blockIdx.x * blockDim.x + threadIdx.x;
    if (e < E) atomicAdd(&cnt[de[e]], 1);
}

__global__ void scan_k1(int* __restrict__ data, int n, int* __restrict__ bsum)
{
    __shared__ int sh[256];
    int base = blockIdx.x * 2048 + threadIdx.x * 8;
    int v[8];
    int run = 0;
#pragma unroll
    for (int k = 0; k < 8; k++) {
        int t = (base + k < n) ? data[base + k] : 0;
        v[k] = run;
        run += t;
    }
    sh[threadIdx.x] = run;
    __syncthreads();
    for (int off = 1; off < 256; off <<= 1) {
        int t = (threadIdx.x >= off) ? sh[threadIdx.x - off] : 0;
        __syncthreads();
        sh[threadIdx.x] += t;
        __syncthreads();
    }
    int excl = sh[threadIdx.x] - run;
#pragma unroll
    for (int k = 0; k < 8; k++)
        if (base + k < n) data[base + k] = v[k] + excl;
    if (threadIdx.x == 255) bsum[blockIdx.x] = sh[255];
}

__global__ void scan_k3m(int* __restrict__ data, int n, const int* __restrict__ bsum,
                         int* __restrict__ cursor, int E)
{
    __shared__ int sb[128];
    __shared__ int spre;
    int blk = (blockIdx.x * 256) >> 11;
    if (threadIdx.x < 128)
        sb[threadIdx.x] = (threadIdx.x < blk) ? bsum[threadIdx.x] : 0;
    __syncthreads();
    if (threadIdx.x == 0) {
        int p = 0;
        for (int b = 0; b < blk; b++) p += sb[b];
        spre = p;
    }
    __syncthreads();
    int i = blockIdx.x * blockDim.x + threadIdx.x;
    if (i < n) {
        int v = data[i] + spre;
        data[i] = v;
        cursor[i] = v;
    }
    if (i == 0) data[n] = E;
}

__global__ void scatter_kernel(const int* __restrict__ se, const int* __restrict__ de,
                               int E, int* __restrict__ cursor, int* __restrict__ ssrc)
{
    int e = blockIdx.x * blockDim.x + threadIdx.x;
    if (e < E) {
        int pos = atomicAdd(&cursor[de[e]], 1);
        ssrc[pos] = se[e];
    }
}

// ---------------- fused softmax-aggregate, CSR (layer 1) -------------------
// half-warp per dst node, 4-edge unrolled, node range [base, end).
__global__ void agg1_kernel(const int* __restrict__ rowptr,
                            const int* __restrict__ ssrc,
                            const float* __restrict__ als,
                            const float* __restrict__ ald,
                            const float* __restrict__ h,
                            const float* __restrict__ bias,
                            float* __restrict__ out, int base, int end)
{
    int gt   = blockIdx.x * blockDim.x + threadIdx.x;
    int node = base + (gt >> 4);
    int li   = gt & 15;
    if (node >= end) return;
    int head = li >> 2;

    float aldv = ald[(size_t)node * 4 + head];

    float e0 = als[(size_t)node * 4 + head] + aldv;
    e0 = e0 > 0.f ? e0 : 0.2f * e0;
    float ex = __expf(e0);
    float den = ex;
    float4 hv = ((const float4*)(h + (size_t)node * 64))[li];
    float4 acc = make_float4(ex * hv.x, ex * hv.y, ex * hv.z, ex * hv.w);

    int j0 = rowptr[node], j1 = rowptr[node + 1];
    int j = j0;
    for (; j + 4 <= j1; j += 4) {
        int s0 = ssrc[j], s1 = ssrc[j + 1], s2 = ssrc[j + 2], s3 = ssrc[j + 3];
        float ea = als[(size_t)s0 * 4 + head];
        float eb = als[(size_t)s1 * 4 + head];
        float ec = als[(size_t)s2 * 4 + head];
        float ed = als[(size_t)s3 * 4 + head];
        float4 v0 = ((const float4*)(h + (size_t)s0 * 64))[li];
        float4 v1 = ((const float4*)(h + (size_t)s1 * 64))[li];
        float4 v2 = ((const float4*)(h + (size_t)s2 * 64))[li];
        float4 v3 = ((const float4*)(h + (size_t)s3 * 64))[li];
        ea += aldv; eb += aldv; ec += aldv; ed += aldv;
        ea = ea > 0.f ? ea : 0.2f * ea;
        eb = eb > 0.f ? eb : 0.2f * eb;
        ec = ec > 0.f ? ec : 0.2f * ec;
        ed = ed > 0.f ? ed : 0.2f * ed;
        float w0 = __expf(ea), w1 = __expf(eb), w2 = __expf(ec), w3 = __expf(ed);
        den += (w0 + w1) + (w2 + w3);
        acc.x = fmaf(w0, v0.x, acc.x); acc.y = fmaf(w0, v0.y, acc.y);
        acc.z = fmaf(w0, v0.z, acc.z); acc.w = fmaf(w0, v0.w, acc.w);
        acc.x = fmaf(w1, v1.x, acc.x); acc.y = fmaf(w1, v1.y, acc.y);
        acc.z = fmaf(w1, v1.z, acc.z); acc.w = fmaf(w1, v1.w, acc.w);
        acc.x = fmaf(w2, v2.x, acc.x); acc.y = fmaf(w2, v2.y, acc.y);
        acc.z = fmaf(w2, v2.z, acc.z); acc.w = fmaf(w2, v2.w, acc.w);
        acc.x = fmaf(w3, v3.x, acc.x); acc.y = fmaf(w3, v3.y, acc.y);
        acc.z = fmaf(w3, v3.z, acc.z); acc.w = fmaf(w3, v3.w, acc.w);
    }
    for (; j < j1; j++) {
        int s = ssrc[j];
        float e = als[(size_t)s * 4 + head] + aldv;
        e = e > 0.f ? e : 0.2f * e;
        float w = __expf(e);
        den += w;
        float4 v = ((const float4*)(h + (size_t)s * 64))[li];
        acc.x = fmaf(w, v.x, acc.x);
        acc.y = fmaf(w, v.y, acc.y);
        acc.z = fmaf(w, v.z, acc.z);
        acc.w = fmaf(w, v.w, acc.w);
    }
    float inv = 1.f / den;
    float4 o;
    o.x = acc.x * inv + bias[li * 4 + 0];
    o.y = acc.y * inv + bias[li * 4 + 1];
    o.z = acc.z * inv + bias[li * 4 + 2];
    o.w = acc.w * inv + bias[li * 4 + 3];
    ((float4*)(out + (size_t)node * 64))[li] = o;
}

// ---------------- layer 2: aggregate + head-mean + bias + elu + logsoftmax -
__global__ void agg2_final_kernel(const int* __restrict__ rowptr,
                                  const int* __restrict__ ssrc,
                                  const float* __restrict__ als,
                                  const float* __restrict__ ald,
                                  const float* __restrict__ h,
                                  const float* __restrict__ b2,
                                  float* __restrict__ y, int n)
{
    int lane = threadIdx.x & 31;
    int node = (blockIdx.x * blockDim.x + threadIdx.x) >> 5;
    if (node >= n) return;
    int head = lane >> 3;

    float aldv = ald[(size_t)node * 4 + head];

    float e0 = als[(size_t)node * 4 + head] + aldv;
    e0 = e0 > 0.f ? e0 : 0.2f * e0;
    float ex = __expf(e0);
    float den = ex;
    float4 hv = ((const float4*)(h + (size_t)node * 128))[lane];
    float4 acc = make_float4(ex * hv.x, ex * hv.y, ex * hv.z, ex * hv.w);

    int j0 = rowptr[node], j1 = rowptr[node + 1];
    int j = j0;
    for (; j + 4 <= j1; j += 4) {
        int s0 = ssrc[j], s1 = ssrc[j + 1], s2 = ssrc[j + 2], s3 = ssrc[j + 3];
        float ea = als[(size_t)s0 * 4 + head];
        float eb = als[(size_t)s1 * 4 + head];
        float ec = als[(size_t)s2 * 4 + head];
        float ed = als[(size_t)s3 * 4 + head];
        float4 v0 = ((const float4*)(h + (size_t)s0 * 128))[lane];
        float4 v1 = ((const float4*)(h + (size_t)s1 * 128))[lane];
        float4 v2 = ((const float4*)(h + (size_t)s2 * 128))[lane];
        float4 v3 = ((const float4*)(h + (size_t)s3 * 128))[lane];
        ea += aldv; eb += aldv; ec += aldv; ed += aldv;
        ea = ea > 0.f ? ea : 0.2f * ea;
        eb = eb > 0.f ? eb : 0.2f * eb;
        ec = ec > 0.f ? ec : 0.2f * ec;
        ed = ed > 0.f ? ed : 0.2f * ed;
        float w0 = __expf(ea), w1 = __expf(eb), w2 = __expf(ec), w3 = __expf(ed);
        den += (w0 + w1) + (w2 + w3);
        acc.x = fmaf(w0, v0.x, acc.x); acc.y = fmaf(w0, v0.y, acc.y);
        acc.z = fmaf(w0, v0.z, acc.z); acc.w = fmaf(w0, v0.w, acc.w);
        acc.x = fmaf(w1, v1.x, acc.x); acc.y = fmaf(w1, v1.y, acc.y);
        acc.z = fmaf(w1, v1.z, acc.z); acc.w = fmaf(w1, v1.w, acc.w);
        acc.x = fmaf(w2, v2.x, acc.x); acc.y = fmaf(w2, v2.y, acc.y);
        acc.z = fmaf(w2, v2.z, acc.z); acc.w = fmaf(w2, v2.w, acc.w);
        acc.x = fmaf(w3, v3.x, acc.x); acc.y = fmaf(w3, v3.y, acc.y);
        acc.z = fmaf(w3, v3.z, acc.z); acc.w = fmaf(w3, v3.w, acc.w);
    }
    for (; j < j1; j++) {
        int s = ssrc[j];
        float e = als[(size_t)s * 4 + head] + aldv;
        e = e > 0.f ? e : 0.2f * e;
        float w = __expf(e);
        den += w;
        float4 v = ((const float4*)(h + (size_t)s * 128))[lane];
        acc.x = fmaf(w, v.x, acc.x);
        acc.y = fmaf(w, v.y, acc.y);
        acc.z = fmaf(w, v.z, acc.z);
        acc.w = fmaf(w, v.w, acc.w);
    }
    float inv = 1.f / den;
    float4 v = make_float4(acc.x * inv, acc.y * inv, acc.z * inv, acc.w * inv);

    v.x += __shfl_xor_sync(0xffffffffu, v.x, 8);
    v.y += __shfl_xor_sync(0xffffffffu, v.y, 8);
    v.z += __shfl_xor_sync(0xffffffffu, v.z, 8);
    v.w += __shfl_xor_sync(0xffffffffu, v.w, 8);
    v.x += __shfl_xor_sync(0xffffffffu, v.x, 16);
    v.y += __shfl_xor_sync(0xffffffffu, v.y, 16);
    v.z += __shfl_xor_sync(0xffffffffu, v.z, 16);
    v.w += __shfl_xor_sync(0xffffffffu, v.w, 16);
    int c0 = (lane & 7) * 4;
    v.x = 0.25f * v.x + b2[c0 + 0];
    v.y = 0.25f * v.y + b2[c0 + 1];
    v.z = 0.25f * v.z + b2[c0 + 2];
    v.w = 0.25f * v.w + b2[c0 + 3];
    v.x = v.x > 0.f ? v.x : expm1f(v.x);
    v.y = v.y > 0.f ? v.y : expm1f(v.y);
    v.z = v.z > 0.f ? v.z : expm1f(v.z);
    v.w = v.w > 0.f ? v.w : expm1f(v.w);
    float m = fmaxf(fmaxf(v.x, v.y), fmaxf(v.z, v.w));
#pragma unroll
    for (int off = 1; off < 8; off <<= 1)
        m = fmaxf(m, __shfl_xor_sync(0xffffffffu, m, off));
    float s = expf(v.x - m) + expf(v.y - m) + expf(v.z - m) + expf(v.w - m);
#pragma unroll
    for (int off = 1; off < 8; off <<= 1)
        s += __shfl_xor_sync(0xffffffffu, s, off);
    float ls = m + logf(s);
    if (lane < 8) {
        float4 o = make_float4(v.x - ls, v.y - ls, v.z - ls, v.w - ls);
        ((float4*)(y + (size_t)node * 32))[lane] = o;
    }
}

// ---------------------------------------------------------------------------
extern "C" void kernel_launch(void* const* d_in, const int* in_sizes, int n_in,
                              void* d_out, int out_size)
{
    const float* x   = (const float*)d_in[0];
    const int*   ei  = (const int*)d_in[1];
    const float* W1  = (const float*)d_in[2];
    const float* as1 = (const float*)d_in[3];
    const float* ad1 = (const float*)d_in[4];
    const float* b1  = (const float*)d_in[5];
    const float* W2  = (const float*)d_in[6];
    const float* as2 = (const float*)d_in[7];
    const float* ad2 = (const float*)d_in[8];
    const float* b2  = (const float*)d_in[9];
    float*       y   = (float*)d_out;

    const int n = in_sizes[0] / 128;
    const int E = in_sizes[1] / 2;
    const int* se = ei;
    const int* de = ei + E;

    float *h1, *als1, *ald1, *out1, *h2, *als2, *ald2;
    int *rowptr, *cursor, *bsum, *ssrc;
    cudaGetSymbolAddress((void**)&h1,     g_h1);
    cudaGetSymbolAddress((void**)&als1,   g_als1);
    cudaGetSymbolAddress((void**)&ald1,   g_ald1);
    cudaGetSymbolAddress((void**)&out1,   g_out1);
    cudaGetSymbolAddress((void**)&h2,     g_h2);
    cudaGetSymbolAddress((void**)&als2,   g_als2);
    cudaGetSymbolAddress((void**)&ald2,   g_ald2);
    cudaGetSymbolAddress((void**)&rowptr, g_rowptr);
    cudaGetSymbolAddress((void**)&cursor, g_cursor);
    cudaGetSymbolAddress((void**)&bsum,   g_bsum);
    cudaGetSymbolAddress((void**)&ssrc,   g_ssrc);

    // side stream + events (created once, reused across capture replays)
    static cudaStream_t s2 = nullptr;
    static cudaEvent_t evFork = nullptr, evJoin = nullptr;
    static cudaEvent_t evFork2 = nullptr, evJoin2 = nullptr;
    if (!s2) {
        cudaStreamCreateWithFlags(&s2, cudaStreamNonBlocking);
        cudaEventCreateWithFlags(&evFork,  cudaEventDisableTiming);
        cudaEventCreateWithFlags(&evJoin,  cudaEventDisableTiming);
        cudaEventCreateWithFlags(&evFork2, cudaEventDisableTiming);
        cudaEventCreateWithFlags(&evJoin2, cudaEventDisableTiming);
    }

    const int nb = (n + 2047) / 2048;
    // node split for the agg1/gemm2 pipeline (~40%, multiple of 128)
    int n0 = (int)((long long)n * 2 / 5);
    n0 = (n0 + 127) & ~127;
    if (n0 > n) n0 = n;
    const int n1 = n - n0;

    // ---- fork: CSR build on s2, concurrent with gemm1 on main ----
    cudaEventRecord(evFork, 0);
    cudaStreamWaitEvent(s2, evFork, 0);
    cudaMemsetAsync(rowptr, 0, (size_t)n * sizeof(int), s2);
    hist_kernel<<<(E + 255) / 256, 256, 0, s2>>>(de, E, rowptr);           // 1
    scan_k1<<<nb, 256, 0, s2>>>(rowptr, n, bsum);                          // 2
    scan_k3m<<<(n + 255) / 256, 256, 0, s2>>>(rowptr, n, bsum, cursor, E); // 3

    gemm_kernel<128, 64, false>                                            // 4 (main)
        <<<dim3((n + 127) / 128, 1), 256>>>(x, W1, nullptr, as1, ad1,
                                            h1, als1, ald1, n);

    scatter_kernel<<<(E + 255) / 256, 256, 0, s2>>>(se, de, E, cursor, ssrc); // 5
    cudaEventRecord(evJoin, s2);
    cudaStreamWaitEvent(0, evJoin, 0);

    // ---- agg1 chunk0 [0, n0) on main ----
    agg1_kernel<<<(int)(((long long)n0 * 16 + 255) / 256), 256>>>(
        rowptr, ssrc, als1, ald1, h1, b1, out1, 0, n0);                    // 6

    // ---- fork2: agg1 chunk1 [n0, n) on s2, concurrent with gemm2 chunk0 --
    cudaEventRecord(evFork2, 0);
    cudaStreamWaitEvent(s2, evFork2, 0);
    if (n1 > 0)
        agg1_kernel<<<(int)(((long long)n1 * 16 + 255) / 256), 256, 0, s2>>>(
            rowptr, ssrc, als1, ald1, h1, b1, out1, n0, n);                // 7 (s2)
    cudaEventRecord(evJoin2, s2);

    // gemm2 chunk0: rows [0, n0) (main, concurrent with agg1 chunk1)
    gemm_kernel<64, 128, true>                                             // 8 (main)
        <<<dim3((n0 + 127) / 128, 2), 256>>>(out1, W2, b1, as2, ad2,
                                             h2, als2, ald2, n0);

    cudaStreamWaitEvent(0, evJoin2, 0);

    // gemm2 chunk1: rows [n0, n)
    if (n1 > 0)
        gemm_kernel<64, 128, true>                                         // 9
            <<<dim3((n1 + 127) / 128, 2), 256>>>(out1 + (size_t)n0 * 64, W2, b1,
                                                 as2, ad2,
                                                 h2 + (size_t)n0 * 128,
                                                 als2 + (size_t)n0 * 4,
                                                 ald2 + (size_t)n0 * 4, n1);

    // ---- layer 2 aggregation + epilogue ----
    agg2_final_kernel<<<(int)(((long long)n * 32 + 255) / 256), 256>>>(
        rowptr, ssrc, als2, ald2, h2, b2, y, n);                           // 10
}